// round 15
// baseline (speedup 1.0000x reference)
#include <cuda_runtime.h>
#include <cuda_bf16.h>
#include <cstdint>
#include <cstddef>

#define Bz 4
#define Sq 2048
#define Dm 512
#define Hh 8
#define DKh 64
#define Mrows (Bz*Sq)   // 8192

// ======================= scratch (__device__ globals) =======================
__device__ __nv_bfloat16 g_wq_hi[Dm*Dm], g_wq_lo[Dm*Dm];
__device__ __nv_bfloat16 g_wk_hi[Dm*Dm], g_wk_lo[Dm*Dm];
__device__ __nv_bfloat16 g_wv_hi[Dm*Dm], g_wv_lo[Dm*Dm];
__device__ __nv_bfloat16 g_wf_hi[Dm*Dm], g_wf_lo[Dm*Dm];
__device__ __nv_bfloat16 g_qh_hi[Mrows*Dm], g_qh_lo[Mrows*Dm];   // (B,H,S,64)
__device__ __nv_bfloat16 g_kh_hi[Mrows*Dm], g_kh_lo[Mrows*Dm];   // (B,H,S,64)
__device__ __nv_bfloat16 g_vt_hi[Mrows*Dm];                      // (B,H,64,S)
__device__ float g_ao[Mrows*Dm];                                 // attention out fp32 (B,S,D)
__device__ float g_fc[Mrows*Dm];
__device__ float g_ew[Bz*Sq];

// ======================= helpers =======================
__device__ __forceinline__ uint32_t smem_u32(const void* p) {
    uint32_t a;
    asm("{ .reg .u64 t; cvta.to.shared.u64 t, %1; cvt.u32.u64 %0, t; }" : "=r"(a) : "l"(p));
    return a;
}
__device__ __forceinline__ void ldsm4(uint32_t* r, uint32_t addr) {
    asm volatile("ldmatrix.sync.aligned.m8n8.x4.shared.b16 {%0,%1,%2,%3}, [%4];"
        : "=r"(r[0]), "=r"(r[1]), "=r"(r[2]), "=r"(r[3]) : "r"(addr));
}
__device__ __forceinline__ void mma16816(float* d, const uint32_t* a, const uint32_t* b) {
    asm volatile("mma.sync.aligned.m16n8k16.row.col.f32.bf16.bf16.f32 "
        "{%0,%1,%2,%3}, {%4,%5,%6,%7}, {%8,%9}, {%0,%1,%2,%3};"
        : "+f"(d[0]), "+f"(d[1]), "+f"(d[2]), "+f"(d[3])
        : "r"(a[0]), "r"(a[1]), "r"(a[2]), "r"(a[3]), "r"(b[0]), "r"(b[1]));
}
// pack two floats into bf16x2 (v0 -> low half)
__device__ __forceinline__ uint32_t pk(float v0, float v1) {
    uint32_t r;
    asm("cvt.rn.bf16x2.f32 %0, %1, %2;" : "=r"(r) : "f"(v1), "f"(v0));
    return r;
}
__device__ __forceinline__ float resid_f(float v) {
    return v - __bfloat162float(__float2bfloat16(v));
}
__device__ __forceinline__ uint32_t pack_bf2(__nv_bfloat16 a, __nv_bfloat16 b) {
    __nv_bfloat162 v; v.x = a; v.y = b;
    return *reinterpret_cast<uint32_t*>(&v);
}

// ======================= K0: entropy weights =======================
__global__ void ew_kernel(const float* __restrict__ We, const float* __restrict__ ent) {
    int i = blockIdx.x * 256 + threadIdx.x;
    int s = i & (Sq - 1);
    g_ew[i] = 8.0f * __expf(We[s] * ent[i]);
}

// ======================= fused weight splits: fp32 -> bf16 hi/lo =======================
// grid (256, 4): blockIdx.y selects {Wq, Wk, Wv, Wfc}
__global__ void wsplit_kernel(const float* __restrict__ Wq, const float* __restrict__ Wk,
                              const float* __restrict__ Wv, const float* __restrict__ Wfc) {
    int which = blockIdx.y;
    const float* src;
    __nv_bfloat16 *hi, *lo;
    switch (which) {
        case 0: src = Wq;  hi = g_wq_hi; lo = g_wq_lo; break;
        case 1: src = Wk;  hi = g_wk_hi; lo = g_wk_lo; break;
        case 2: src = Wv;  hi = g_wv_hi; lo = g_wv_lo; break;
        default: src = Wfc; hi = g_wf_hi; lo = g_wf_lo; break;
    }
    int i = blockIdx.x * 256 + threadIdx.x;   // i < Dm*Dm/4 = 65536
    float4 v = ((const float4*)src)[i];
    __nv_bfloat16 h0 = __float2bfloat16(v.x), h1 = __float2bfloat16(v.y);
    __nv_bfloat16 h2 = __float2bfloat16(v.z), h3 = __float2bfloat16(v.w);
    __nv_bfloat16 l0 = __float2bfloat16(v.x - __bfloat162float(h0));
    __nv_bfloat16 l1 = __float2bfloat16(v.y - __bfloat162float(h1));
    __nv_bfloat16 l2 = __float2bfloat16(v.z - __bfloat162float(h2));
    __nv_bfloat16 l3 = __float2bfloat16(v.w - __bfloat162float(h3));
    ((uint2*)hi)[i] = make_uint2(pack_bf2(h0, h1), pack_bf2(h2, h3));
    ((uint2*)lo)[i] = make_uint2(pack_bf2(l0, l1), pack_bf2(l2, l3));
}

// ======================= GEMM: C[8192,512] = A * W^T (fused 3-pass hi/lo) =======================
// CTA 128x128, BK=32, 8 warps (4x2), warp tile 32x64.
// OCC=2: single smem buffer, inline load->split->store, latency covered by co-resident CTA.
#define GP 80
#define GTILE 10240       // 128 rows x 80B
#define GBUF  (4*GTILE)   // tiles {Ah, Al, Wh, Wl} = 40960
#define GSMEM GBUF

__global__ __launch_bounds__(256, 2) void gemm_tc(const float* __restrict__ Aext,
                                                  const float* __restrict__ bias,
                                                  const float* __restrict__ resid,
                                                  int mode) {
    extern __shared__ __align__(16) char gsm[];
    const int t = threadIdx.x, lane = t & 31, wid = t >> 5;
    const int wm = wid & 3, wn = wid >> 2;
    const int lr = lane >> 2, lc = lane & 3;
    const int mbase = blockIdx.y * 128, nbase = blockIdx.x * 128;

    const float* Ap = (mode == 3) ? g_ao : Aext;
    const __nv_bfloat16 *Wh, *Wl;
    switch (mode) {
        case 0: Wh = g_wq_hi; Wl = g_wq_lo; break;
        case 1: Wh = g_wk_hi; Wl = g_wk_lo; break;
        case 2: Wh = g_wv_hi; Wl = g_wv_lo; break;
        default: Wh = g_wf_hi; Wl = g_wf_lo; break;
    }

    float acc[2][8][4];
#pragma unroll
    for (int i = 0; i < 2; i++)
#pragma unroll
        for (int j = 0; j < 8; j++)
#pragma unroll
            for (int q = 0; q < 4; q++) acc[i][j][q] = 0.f;

    const int a_row = t >> 3, a_sg = t & 7;       // A: 128 rows x 8 segs (uint4 of fp32)

    for (int c = 0; c < 16; c++) {
        int kk = c * 32;
        __syncthreads();   // previous iteration's readers done before overwrite
#pragma unroll
        for (int i = 0; i < 4; i++) {       // A fp32 -> split -> {Ah, Al}
            int row = a_row + i * 32;
            float4 v = *(const float4*)(Ap + (size_t)(mbase + row) * Dm + kk + a_sg * 4);
            uint2 hi = make_uint2(pk(v.x, v.y), pk(v.z, v.w));
            uint2 lo = make_uint2(pk(resid_f(v.x), resid_f(v.y)), pk(resid_f(v.z), resid_f(v.w)));
            *(uint2*)(gsm + row * GP + a_sg * 8) = hi;
            *(uint2*)(gsm + GTILE + row * GP + a_sg * 8) = lo;
        }
#pragma unroll
        for (int i = 0; i < 4; i++) {       // Wh, Wl bf16 tiles
            int id = t + i * 256;
            int tile = id >> 9, w = id & 511, row = w >> 2, sg = w & 3;
            const __nv_bfloat16* src = (tile == 0) ? Wh : Wl;
            uint4 vv = *(const uint4*)(src + (size_t)(nbase + row) * Dm + kk + sg * 8);
            *(uint4*)(gsm + (2 + tile) * GTILE + row * GP + sg * 16) = vv;
        }
        __syncthreads();

        uint32_t bufu = smem_u32(gsm);
#pragma unroll
        for (int ks = 0; ks < 2; ks++) {
            uint32_t afh[2][4], afl[2][4];
            uint32_t arow = bufu + (wm * 32 + (lane & 15)) * GP + ks * 32 + (lane >> 4) * 16;
            ldsm4(afh[0], arow);
            ldsm4(afh[1], arow + 16 * GP);
            ldsm4(afl[0], arow + GTILE);
            ldsm4(afl[1], arow + GTILE + 16 * GP);
            uint32_t brow = bufu + 2 * GTILE + (wn * 64 + (lane & 15)) * GP + ks * 32 + (lane >> 4) * 16;
            uint32_t wh4[2][4];
            ldsm4(wh4[0], brow);
#pragma unroll
            for (int j2 = 0; j2 < 4; j2++) {
                int cur = j2 & 1;
                uint32_t wl4[4];
                ldsm4(wl4, brow + GTILE + j2 * 16 * GP);
                if (j2 < 3) ldsm4(wh4[cur ^ 1], brow + (j2 + 1) * 16 * GP);
                {
                    uint32_t be[2] = {wh4[cur][0], wh4[cur][2]}, bo[2] = {wh4[cur][1], wh4[cur][3]};
#pragma unroll
                    for (int i = 0; i < 2; i++) {
                        mma16816(acc[i][2 * j2],     afh[i], be);
                        mma16816(acc[i][2 * j2 + 1], afh[i], bo);
                        mma16816(acc[i][2 * j2],     afl[i], be);
                        mma16816(acc[i][2 * j2 + 1], afl[i], bo);
                    }
                }
                {
                    uint32_t be[2] = {wl4[0], wl4[2]}, bo[2] = {wl4[1], wl4[3]};
#pragma unroll
                    for (int i = 0; i < 2; i++) {
                        mma16816(acc[i][2 * j2],     afh[i], be);
                        mma16816(acc[i][2 * j2 + 1], afh[i], bo);
                    }
                }
            }
        }
    }

    // epilogue
#pragma unroll
    for (int i = 0; i < 2; i++) {
        int m0 = mbase + wm * 32 + i * 16 + lr;
        int m1 = m0 + 8;
#pragma unroll
        for (int j = 0; j < 8; j++) {
            int n = nbase + wn * 64 + 8 * j + 2 * lc;
            float b0 = bias[n], b1 = bias[n + 1];
            float v0 = acc[i][j][0] + b0, v1 = acc[i][j][1] + b1;   // row m0
            float v2 = acc[i][j][2] + b0, v3 = acc[i][j][3] + b1;   // row m1
            if (mode == 3) {
                size_t o0 = (size_t)m0 * Dm + n, o1 = (size_t)m1 * Dm + n;
                float2 r0 = *(const float2*)(resid + o0);
                float2 r1 = *(const float2*)(resid + o1);
                *(float2*)(g_fc + o0) = make_float2(v0 + r0.x, v1 + r0.y);
                *(float2*)(g_fc + o1) = make_float2(v2 + r1.x, v3 + r1.y);
            } else if (mode == 2) {
                int h = n >> 6, dl = n & 63;
                int b0_ = m0 >> 11, s0 = m0 & (Sq - 1);
                int b1_ = m1 >> 11, s1 = m1 & (Sq - 1);
                size_t p00 = ((size_t)(b0_ * Hh + h) * DKh + dl) * Sq + s0;
                size_t p10 = ((size_t)(b1_ * Hh + h) * DKh + dl) * Sq + s1;
                g_vt_hi[p00] = __float2bfloat16(v0); g_vt_hi[p00 + Sq] = __float2bfloat16(v1);
                g_vt_hi[p10] = __float2bfloat16(v2); g_vt_hi[p10 + Sq] = __float2bfloat16(v3);
            } else {
                int h = n >> 6, dl = n & 63;
                int b0_ = m0 >> 11, s0 = m0 & (Sq - 1);
                int b1_ = m1 >> 11, s1 = m1 & (Sq - 1);
                size_t o0 = ((size_t)(b0_ * Hh + h) * Sq + s0) * DKh + dl;
                size_t o1 = ((size_t)(b1_ * Hh + h) * Sq + s1) * DKh + dl;
                __nv_bfloat16* oh = (mode == 0) ? g_qh_hi : g_kh_hi;
                __nv_bfloat16* ol = (mode == 0) ? g_qh_lo : g_kh_lo;
                *(uint32_t*)(oh + o0) = pk(v0, v1);
                *(uint32_t*)(ol + o0) = pk(resid_f(v0), resid_f(v1));
                *(uint32_t*)(oh + o1) = pk(v2, v3);
                *(uint32_t*)(ol + o1) = pk(resid_f(v2), resid_f(v3));
            }
        }
    }
}

// ======================= flash attention =======================
// grid (16, 32), 256 thr (8 warps). Tq=128 (warp: 16 rows), Tk=64, dk=64.
// OCC=2: no cross-iteration register prefetch, SINGLE k-tile buffer; each tile
// loaded gmem->reg->smem inside the iteration (latency covered by co-resident CTA).
// Q staged overlapping the k-tile buffer (consumed into registers pre-loop).
// S: 3-pass (QhKh + QhKl + QlKh). PV: 2-pass (PhVh + PlVh).
#define AP 144
#define ATS 9216          // one k-tile: 64*144
#define ABUF (3*ATS)      // {Kh, Kl, Vh} = 27648
#define QTS  18432        // one Q half: 128*144
#define A_BASE 512
#define AT_SMEM (A_BASE + 2*QTS)   // 37376 (> A_BASE+ABUF = 28160)
#define NKT (Sq/64)       // 32

__global__ __launch_bounds__(256, 2) void attn_tc() {
    extern __shared__ char smA[];
    const uint32_t smu = smem_u32(smA);
    const int t = threadIdx.x, lane = t & 31, wid = t >> 5;
    const int lr = lane >> 2, lc = lane & 3;
    const int bh = blockIdx.y, b = bh >> 3;
    const int qbase = blockIdx.x * 128;

    // ---- stage Q (hi/lo) at A_BASE (overlaps k-tile buffer; read pre-loop) ----
    {
        char* qdst = smA + A_BASE;
#pragma unroll
        for (int i = 0; i < 8; i++) {
            int id = t + i * 256;
            int half = id >> 10, w = id & 1023, row = w >> 3, sg = w & 7;
            const __nv_bfloat16* src = half ? g_qh_lo : g_qh_hi;
            *(uint4*)(qdst + half * QTS + row * AP + sg * 16) =
                *(const uint4*)(src + ((size_t)bh * Sq + qbase + row) * DKh + sg * 8);
        }
    }
    __syncthreads();

    uint32_t qhf[4][4], qlf[4][4];
    {
        uint32_t qb = smu + A_BASE + (wid * 16 + (lane & 15)) * AP + (lane >> 4) * 16;
#pragma unroll
        for (int ks = 0; ks < 4; ks++) {
            ldsm4(qhf[ks], qb + ks * 32);
            ldsm4(qlf[ks], qb + ks * 32 + QTS);
        }
    }

    float O[8][4];
#pragma unroll
    for (int j = 0; j < 8; j++)
#pragma unroll
        for (int q = 0; q < 4; q++) O[j][q] = 0.f;
    float m0 = -1e30f, m1 = -1e30f, l0 = 0.f, l1 = 0.f;

    // constant fragment base addresses (single buffer)
    const uint32_t bK  = smu + A_BASE;
    const uint32_t kbh = bK + (lane & 15) * AP + (lane >> 4) * 16;
    const uint32_t kbl = kbh + ATS;
    const uint32_t vbh = kbh + 2 * ATS;
    const int ld_tile = t >> 8, ld_w = t & 511;   // recomputed per i below

    for (int kt = 0; kt < NKT; kt++) {
        // ---- load k-tile gmem -> regs (batched LDGs) ----
        uint4 R[6];
#pragma unroll
        for (int i = 0; i < 6; i++) {
            int id = t + i * 256;
            int tile = id >> 9, w = id & 511, row = w >> 3, sg = w & 7;
            const __nv_bfloat16* src;
            size_t g;
            if (tile == 0)      { src = g_kh_hi; g = ((size_t)bh * Sq + kt * 64 + row) * DKh + sg * 8; }
            else if (tile == 1) { src = g_kh_lo; g = ((size_t)bh * Sq + kt * 64 + row) * DKh + sg * 8; }
            else                { src = g_vt_hi; g = ((size_t)bh * DKh + row) * Sq + kt * 64 + sg * 8; }
            R[i] = *(const uint4*)(src + g);
        }
        float E = 0.f;
        if (t < 64) E = g_ew[(size_t)b * Sq + kt * 64 + t];

        __syncthreads();   // previous tile's readers (or Q-fragment loads) done
#pragma unroll
        for (int i = 0; i < 6; i++) {
            int id = t + i * 256;
            int tile = id >> 9, w = id & 511, row = w >> 3, sg = w & 7;
            *(uint4*)(smA + A_BASE + tile * ATS + row * AP + sg * 16) = R[i];
        }
        if (t < 64) *(float*)(smA + t * 4) = E;
        __syncthreads();

        // ---- S = Q K^T : pipelined fragment loads, K fragments reused by Qh/Ql ----
        float S[8][4];
#pragma unroll
        for (int j = 0; j < 8; j++)
#pragma unroll
            for (int q = 0; q < 4; q++) S[j][q] = 0.f;

        uint32_t kh4[2][4], kl4[2][4];
        ldsm4(kh4[0], kbh);
        ldsm4(kl4[0], kbl);
#pragma unroll
        for (int idx = 0; idx < 16; idx++) {
            int cur = idx & 1;
            if (idx < 15) {
                uint32_t off = (uint32_t)((idx + 1) & 3) * (16 * AP) + (uint32_t)((idx + 1) >> 2) * 32;
                ldsm4(kh4[cur ^ 1], kbh + off);
                ldsm4(kl4[cur ^ 1], kbl + off);
            }
            int ks = idx >> 2, j2 = idx & 3;
            {
                uint32_t be[2] = {kh4[cur][0], kh4[cur][2]}, bo[2] = {kh4[cur][1], kh4[cur][3]};
                mma16816(S[2 * j2],     qhf[ks], be);
                mma16816(S[2 * j2 + 1], qhf[ks], bo);
                mma16816(S[2 * j2],     qlf[ks], be);
                mma16816(S[2 * j2 + 1], qlf[ks], bo);
            }
            {
                uint32_t be[2] = {kl4[cur][0], kl4[cur][2]}, bo[2] = {kl4[cur][1], kl4[cur][3]};
                mma16816(S[2 * j2],     qhf[ks], be);
                mma16816(S[2 * j2 + 1], qhf[ks], bo);
            }
        }

        // ---- softmax (rows lr and lr+8, cols spread over 4 lanes) ----
        const float* ew = (const float*)smA;
        float mt0 = -1e30f, mt1 = -1e30f;
#pragma unroll
        for (int j = 0; j < 8; j++) {
            float2 e = *(const float2*)(ew + 8 * j + 2 * lc);
            S[j][0] *= e.x; S[j][1] *= e.y;
            S[j][2] *= e.x; S[j][3] *= e.y;
            mt0 = fmaxf(mt0, fmaxf(S[j][0], S[j][1]));
            mt1 = fmaxf(mt1, fmaxf(S[j][2], S[j][3]));
        }
        mt0 = fmaxf(mt0, __shfl_xor_sync(0xffffffffu, mt0, 1));
        mt0 = fmaxf(mt0, __shfl_xor_sync(0xffffffffu, mt0, 2));
        mt1 = fmaxf(mt1, __shfl_xor_sync(0xffffffffu, mt1, 1));
        mt1 = fmaxf(mt1, __shfl_xor_sync(0xffffffffu, mt1, 2));
        float mn0 = fmaxf(m0, mt0), mn1 = fmaxf(m1, mt1);
        float al0 = __expf(m0 - mn0), al1 = __expf(m1 - mn1);
        m0 = mn0; m1 = mn1;
        float ps0 = 0.f, ps1 = 0.f;
#pragma unroll
        for (int j = 0; j < 8; j++) {
            S[j][0] = __expf(S[j][0] - mn0); ps0 += S[j][0];
            S[j][1] = __expf(S[j][1] - mn0); ps0 += S[j][1];
            S[j][2] = __expf(S[j][2] - mn1); ps1 += S[j][2];
            S[j][3] = __expf(S[j][3] - mn1); ps1 += S[j][3];
        }
        ps0 += __shfl_xor_sync(0xffffffffu, ps0, 1);
        ps0 += __shfl_xor_sync(0xffffffffu, ps0, 2);
        ps1 += __shfl_xor_sync(0xffffffffu, ps1, 1);
        ps1 += __shfl_xor_sync(0xffffffffu, ps1, 2);
        l0 = l0 * al0 + ps0;
        l1 = l1 * al1 + ps1;
#pragma unroll
        for (int j = 0; j < 8; j++) {
            O[j][0] *= al0; O[j][1] *= al0;
            O[j][2] *= al1; O[j][3] *= al1;
        }

        // ---- P packs (hi/lo), reused directly as mma A operands ----
        uint32_t Ph[8][2], Pl[8][2];
#pragma unroll
        for (int j = 0; j < 8; j++) {
            Ph[j][0] = pk(S[j][0], S[j][1]);
            Ph[j][1] = pk(S[j][2], S[j][3]);
            Pl[j][0] = pk(resid_f(S[j][0]), resid_f(S[j][1]));
            Pl[j][1] = pk(resid_f(S[j][2]), resid_f(S[j][3]));
        }

        // ---- O += P V : 2-pass, pipelined V fragment loads ----
        uint32_t vh4[2][4];
        ldsm4(vh4[0], vbh);
#pragma unroll
        for (int idx = 0; idx < 16; idx++) {
            int cur = idx & 1;
            if (idx < 15) {
                uint32_t off = (uint32_t)((idx + 1) & 3) * (16 * AP) + (uint32_t)((idx + 1) >> 2) * 32;
                ldsm4(vh4[cur ^ 1], vbh + off);
            }
            int ks = idx >> 2, j2 = idx & 3;
            uint32_t a4h[4] = {Ph[2 * ks][0], Ph[2 * ks][1], Ph[2 * ks + 1][0], Ph[2 * ks + 1][1]};
            uint32_t a4l[4] = {Pl[2 * ks][0], Pl[2 * ks][1], Pl[2 * ks + 1][0], Pl[2 * ks + 1][1]};
            uint32_t ve[2] = {vh4[cur][0], vh4[cur][2]}, vo[2] = {vh4[cur][1], vh4[cur][3]};
            mma16816(O[2 * j2],     a4h, ve);
            mma16816(O[2 * j2 + 1], a4h, vo);
            mma16816(O[2 * j2],     a4l, ve);
            mma16816(O[2 * j2 + 1], a4l, vo);
        }
    }

    // ---- finalize + write fp32 into g_ao (B,S,512) ----
    float inv0 = 1.0f / l0, inv1 = 1.0f / l1;
    int row0 = qbase + wid * 16 + lr, row1 = row0 + 8;
    size_t base0 = ((size_t)(b * Sq + row0)) * Dm + (bh & 7) * DKh + 2 * lc;
    size_t base1 = ((size_t)(b * Sq + row1)) * Dm + (bh & 7) * DKh + 2 * lc;
#pragma unroll
    for (int j = 0; j < 8; j++) {
        *(float2*)(g_ao + base0 + 8 * j) = make_float2(O[j][0] * inv0, O[j][1] * inv0);
        *(float2*)(g_ao + base1 + 8 * j) = make_float2(O[j][2] * inv1, O[j][3] * inv1);
    }
}

// ======================= LayerNorm =======================
__global__ __launch_bounds__(128) void ln_kernel(const float* __restrict__ gamma,
                                                 const float* __restrict__ beta,
                                                 float* __restrict__ out) {
    __shared__ float red[4];
    const int row = blockIdx.x, t = threadIdx.x;
    float4 x = *(const float4*)(g_fc + (size_t)row * Dm + t * 4);
    float s = x.x + x.y + x.z + x.w;
#pragma unroll
    for (int off = 16; off > 0; off >>= 1) s += __shfl_xor_sync(0xffffffffu, s, off);
    if ((t & 31) == 0) red[t >> 5] = s;
    __syncthreads();
    float mu = (red[0] + red[1] + red[2] + red[3]) * (1.0f / Dm);
    float d0 = x.x - mu, d1 = x.y - mu, d2 = x.z - mu, d3 = x.w - mu;
    float sq = d0 * d0 + d1 * d1 + d2 * d2 + d3 * d3;
#pragma unroll
    for (int off = 16; off > 0; off >>= 1) sq += __shfl_xor_sync(0xffffffffu, sq, off);
    __syncthreads();
    if ((t & 31) == 0) red[t >> 5] = sq;
    __syncthreads();
    float var = (red[0] + red[1] + red[2] + red[3]) * (1.0f / Dm);
    float inv = rsqrtf(var + 1e-5f);
    int c = t * 4;
    float4 g = *(const float4*)(gamma + c);
    float4 be = *(const float4*)(beta + c);
    *(float4*)(out + (size_t)row * Dm + c) =
        make_float4(d0 * inv * g.x + be.x, d1 * inv * g.y + be.y,
                    d2 * inv * g.z + be.z, d3 * inv * g.w + be.w);
}

// ======================= launch =======================
extern "C" void kernel_launch(void* const* d_in, const int* in_sizes, int n_in,
                              void* d_out, int out_size) {
    const float* Q   = (const float*)d_in[0];
    const float* K   = (const float*)d_in[1];
    const float* V   = (const float*)d_in[2];
    const float* ent = (const float*)d_in[3];
    const float* Wq  = (const float*)d_in[4];
    const float* bq  = (const float*)d_in[5];
    const float* Wk  = (const float*)d_in[6];
    const float* bk  = (const float*)d_in[7];
    const float* Wv  = (const float*)d_in[8];
    const float* bv  = (const float*)d_in[9];
    const float* Wfc = (const float*)d_in[10];
    const float* bfc = (const float*)d_in[11];
    const float* We  = (const float*)d_in[12];
    const float* gam = (const float*)d_in[13];
    const float* bet = (const float*)d_in[14];
    float* out = (float*)d_out;

    cudaFuncSetAttribute(attn_tc, cudaFuncAttributeMaxDynamicSharedMemorySize, AT_SMEM);
    cudaFuncSetAttribute(gemm_tc, cudaFuncAttributeMaxDynamicSharedMemorySize, GSMEM);

    ew_kernel<<<(Bz * Sq) / 256, 256>>>(We, ent);
    wsplit_kernel<<<dim3(256, 4), 256>>>(Wq, Wk, Wv, Wfc);

    dim3 gg(Dm / 128, Mrows / 128);   // (4, 64)
    gemm_tc<<<gg, 256, GSMEM>>>(Q, bq, nullptr, 0);
    gemm_tc<<<gg, 256, GSMEM>>>(K, bk, nullptr, 1);
    gemm_tc<<<gg, 256, GSMEM>>>(V, bv, nullptr, 2);

    attn_tc<<<dim3(Sq / 128, Bz * Hh), 256, AT_SMEM>>>();

    gemm_tc<<<gg, 256, GSMEM>>>(nullptr, bfc, Q, 3);
    ln_kernel<<<Mrows, 128>>>(gam, bet, out);
}

// round 16
// speedup vs baseline: 1.0651x; 1.0651x over previous
#include <cuda_runtime.h>
#include <cuda_bf16.h>
#include <cstdint>
#include <cstddef>

#define Bz 4
#define Sq 2048
#define Dm 512
#define Hh 8
#define DKh 64
#define Mrows (Bz*Sq)   // 8192

// ======================= scratch (__device__ globals) =======================
__device__ __nv_bfloat16 g_wq_hi[Dm*Dm], g_wq_lo[Dm*Dm];
__device__ __nv_bfloat16 g_wk_hi[Dm*Dm], g_wk_lo[Dm*Dm];
__device__ __nv_bfloat16 g_wv_hi[Dm*Dm], g_wv_lo[Dm*Dm];
__device__ __nv_bfloat16 g_wf_hi[Dm*Dm], g_wf_lo[Dm*Dm];
__device__ __nv_bfloat16 g_qh_hi[Mrows*Dm], g_qh_lo[Mrows*Dm];   // (B,H,S,64)
__device__ __nv_bfloat16 g_kh_hi[Mrows*Dm], g_kh_lo[Mrows*Dm];   // (B,H,S,64)
__device__ __nv_bfloat16 g_vt_hi[Mrows*Dm];                      // (B,H,64,S)
__device__ float g_ao[Mrows*Dm];                                 // attention out fp32 (B,S,D)
__device__ float g_fc[Mrows*Dm];
__device__ float g_ew[Bz*Sq];

// ======================= helpers =======================
__device__ __forceinline__ uint32_t smem_u32(const void* p) {
    uint32_t a;
    asm("{ .reg .u64 t; cvta.to.shared.u64 t, %1; cvt.u32.u64 %0, t; }" : "=r"(a) : "l"(p));
    return a;
}
__device__ __forceinline__ void ldsm4(uint32_t* r, uint32_t addr) {
    asm volatile("ldmatrix.sync.aligned.m8n8.x4.shared.b16 {%0,%1,%2,%3}, [%4];"
        : "=r"(r[0]), "=r"(r[1]), "=r"(r[2]), "=r"(r[3]) : "r"(addr));
}
__device__ __forceinline__ void mma16816(float* d, const uint32_t* a, const uint32_t* b) {
    asm volatile("mma.sync.aligned.m16n8k16.row.col.f32.bf16.bf16.f32 "
        "{%0,%1,%2,%3}, {%4,%5,%6,%7}, {%8,%9}, {%0,%1,%2,%3};"
        : "+f"(d[0]), "+f"(d[1]), "+f"(d[2]), "+f"(d[3])
        : "r"(a[0]), "r"(a[1]), "r"(a[2]), "r"(a[3]), "r"(b[0]), "r"(b[1]));
}
// pack two floats into bf16x2 (v0 -> low half)
__device__ __forceinline__ uint32_t pk(float v0, float v1) {
    uint32_t r;
    asm("cvt.rn.bf16x2.f32 %0, %1, %2;" : "=r"(r) : "f"(v1), "f"(v0));
    return r;
}
__device__ __forceinline__ float resid_f(float v) {
    return v - __bfloat162float(__float2bfloat16(v));
}
__device__ __forceinline__ uint32_t pack_bf2(__nv_bfloat16 a, __nv_bfloat16 b) {
    __nv_bfloat162 v; v.x = a; v.y = b;
    return *reinterpret_cast<uint32_t*>(&v);
}

// ======================= K0: entropy weights =======================
__global__ void ew_kernel(const float* __restrict__ We, const float* __restrict__ ent) {
    int i = blockIdx.x * 256 + threadIdx.x;
    int s = i & (Sq - 1);
    g_ew[i] = 8.0f * __expf(We[s] * ent[i]);
}

// ======================= fused weight splits: fp32 -> bf16 hi/lo =======================
// grid (256, 4): blockIdx.y selects {Wq, Wk, Wv, Wfc}
__global__ void wsplit_kernel(const float* __restrict__ Wq, const float* __restrict__ Wk,
                              const float* __restrict__ Wv, const float* __restrict__ Wfc) {
    int which = blockIdx.y;
    const float* src;
    __nv_bfloat16 *hi, *lo;
    switch (which) {
        case 0: src = Wq;  hi = g_wq_hi; lo = g_wq_lo; break;
        case 1: src = Wk;  hi = g_wk_hi; lo = g_wk_lo; break;
        case 2: src = Wv;  hi = g_wv_hi; lo = g_wv_lo; break;
        default: src = Wfc; hi = g_wf_hi; lo = g_wf_lo; break;
    }
    int i = blockIdx.x * 256 + threadIdx.x;   // i < Dm*Dm/4 = 65536
    float4 v = ((const float4*)src)[i];
    __nv_bfloat16 h0 = __float2bfloat16(v.x), h1 = __float2bfloat16(v.y);
    __nv_bfloat16 h2 = __float2bfloat16(v.z), h3 = __float2bfloat16(v.w);
    __nv_bfloat16 l0 = __float2bfloat16(v.x - __bfloat162float(h0));
    __nv_bfloat16 l1 = __float2bfloat16(v.y - __bfloat162float(h1));
    __nv_bfloat16 l2 = __float2bfloat16(v.z - __bfloat162float(h2));
    __nv_bfloat16 l3 = __float2bfloat16(v.w - __bfloat162float(h3));
    ((uint2*)hi)[i] = make_uint2(pack_bf2(h0, h1), pack_bf2(h2, h3));
    ((uint2*)lo)[i] = make_uint2(pack_bf2(l0, l1), pack_bf2(l2, l3));
}

// ======================= GEMM: C[8192,512] = A * W^T (fused 3-pass hi/lo) =======================
// CTA 128x128, BK=32, 8 warps (4x2), warp tile 32x64.
// OCC=2: single smem buffer, inline load->split->store, latency covered by co-resident CTA.
// mode_arg == -1: fused QKV launch, mode = blockIdx.z (0/1/2). Otherwise mode = mode_arg.
#define GP 80
#define GTILE 10240       // 128 rows x 80B
#define GBUF  (4*GTILE)   // tiles {Ah, Al, Wh, Wl} = 40960
#define GSMEM GBUF

__global__ __launch_bounds__(256, 2) void gemm_tc(const float* __restrict__ A0,
                                                  const float* __restrict__ A1,
                                                  const float* __restrict__ A2,
                                                  const float* __restrict__ b0p,
                                                  const float* __restrict__ b1p,
                                                  const float* __restrict__ b2p,
                                                  const float* __restrict__ resid,
                                                  int mode_arg) {
    extern __shared__ __align__(16) char gsm[];
    const int t = threadIdx.x, lane = t & 31, wid = t >> 5;
    const int wm = wid & 3, wn = wid >> 2;
    const int lr = lane >> 2, lc = lane & 3;
    const int mbase = blockIdx.y * 128, nbase = blockIdx.x * 128;

    const int mode = (mode_arg < 0) ? (int)blockIdx.z : mode_arg;
    const float* Ap;
    const float* bias;
    const __nv_bfloat16 *Wh, *Wl;
    switch (mode) {
        case 0: Ap = A0; bias = b0p; Wh = g_wq_hi; Wl = g_wq_lo; break;
        case 1: Ap = A1; bias = b1p; Wh = g_wk_hi; Wl = g_wk_lo; break;
        case 2: Ap = A2; bias = b2p; Wh = g_wv_hi; Wl = g_wv_lo; break;
        default: Ap = g_ao; bias = b0p; Wh = g_wf_hi; Wl = g_wf_lo; break;
    }

    float acc[2][8][4];
#pragma unroll
    for (int i = 0; i < 2; i++)
#pragma unroll
        for (int j = 0; j < 8; j++)
#pragma unroll
            for (int q = 0; q < 4; q++) acc[i][j][q] = 0.f;

    const int a_row = t >> 3, a_sg = t & 7;       // A: 128 rows x 8 segs (uint4 of fp32)

    for (int c = 0; c < 16; c++) {
        int kk = c * 32;
        __syncthreads();   // previous iteration's readers done before overwrite
#pragma unroll
        for (int i = 0; i < 4; i++) {       // A fp32 -> split -> {Ah, Al}
            int row = a_row + i * 32;
            float4 v = *(const float4*)(Ap + (size_t)(mbase + row) * Dm + kk + a_sg * 4);
            uint2 hi = make_uint2(pk(v.x, v.y), pk(v.z, v.w));
            uint2 lo = make_uint2(pk(resid_f(v.x), resid_f(v.y)), pk(resid_f(v.z), resid_f(v.w)));
            *(uint2*)(gsm + row * GP + a_sg * 8) = hi;
            *(uint2*)(gsm + GTILE + row * GP + a_sg * 8) = lo;
        }
#pragma unroll
        for (int i = 0; i < 4; i++) {       // Wh, Wl bf16 tiles
            int id = t + i * 256;
            int tile = id >> 9, w = id & 511, row = w >> 2, sg = w & 3;
            const __nv_bfloat16* src = (tile == 0) ? Wh : Wl;
            uint4 vv = *(const uint4*)(src + (size_t)(nbase + row) * Dm + kk + sg * 8);
            *(uint4*)(gsm + (2 + tile) * GTILE + row * GP + sg * 16) = vv;
        }
        __syncthreads();

        uint32_t bufu = smem_u32(gsm);
#pragma unroll
        for (int ks = 0; ks < 2; ks++) {
            uint32_t afh[2][4], afl[2][4];
            uint32_t arow = bufu + (wm * 32 + (lane & 15)) * GP + ks * 32 + (lane >> 4) * 16;
            ldsm4(afh[0], arow);
            ldsm4(afh[1], arow + 16 * GP);
            ldsm4(afl[0], arow + GTILE);
            ldsm4(afl[1], arow + GTILE + 16 * GP);
            uint32_t brow = bufu + 2 * GTILE + (wn * 64 + (lane & 15)) * GP + ks * 32 + (lane >> 4) * 16;
            uint32_t wh4[2][4];
            ldsm4(wh4[0], brow);
#pragma unroll
            for (int j2 = 0; j2 < 4; j2++) {
                int cur = j2 & 1;
                uint32_t wl4[4];
                ldsm4(wl4, brow + GTILE + j2 * 16 * GP);
                if (j2 < 3) ldsm4(wh4[cur ^ 1], brow + (j2 + 1) * 16 * GP);
                {
                    uint32_t be[2] = {wh4[cur][0], wh4[cur][2]}, bo[2] = {wh4[cur][1], wh4[cur][3]};
#pragma unroll
                    for (int i = 0; i < 2; i++) {
                        mma16816(acc[i][2 * j2],     afh[i], be);
                        mma16816(acc[i][2 * j2 + 1], afh[i], bo);
                        mma16816(acc[i][2 * j2],     afl[i], be);
                        mma16816(acc[i][2 * j2 + 1], afl[i], bo);
                    }
                }
                {
                    uint32_t be[2] = {wl4[0], wl4[2]}, bo[2] = {wl4[1], wl4[3]};
#pragma unroll
                    for (int i = 0; i < 2; i++) {
                        mma16816(acc[i][2 * j2],     afh[i], be);
                        mma16816(acc[i][2 * j2 + 1], afh[i], bo);
                    }
                }
            }
        }
    }

    // epilogue
#pragma unroll
    for (int i = 0; i < 2; i++) {
        int m0 = mbase + wm * 32 + i * 16 + lr;
        int m1 = m0 + 8;
#pragma unroll
        for (int j = 0; j < 8; j++) {
            int n = nbase + wn * 64 + 8 * j + 2 * lc;
            float b0 = bias[n], b1 = bias[n + 1];
            float v0 = acc[i][j][0] + b0, v1 = acc[i][j][1] + b1;   // row m0
            float v2 = acc[i][j][2] + b0, v3 = acc[i][j][3] + b1;   // row m1
            if (mode == 3) {
                size_t o0 = (size_t)m0 * Dm + n, o1 = (size_t)m1 * Dm + n;
                float2 r0 = *(const float2*)(resid + o0);
                float2 r1 = *(const float2*)(resid + o1);
                *(float2*)(g_fc + o0) = make_float2(v0 + r0.x, v1 + r0.y);
                *(float2*)(g_fc + o1) = make_float2(v2 + r1.x, v3 + r1.y);
            } else if (mode == 2) {
                int h = n >> 6, dl = n & 63;
                int b0_ = m0 >> 11, s0 = m0 & (Sq - 1);
                int b1_ = m1 >> 11, s1 = m1 & (Sq - 1);
                size_t p00 = ((size_t)(b0_ * Hh + h) * DKh + dl) * Sq + s0;
                size_t p10 = ((size_t)(b1_ * Hh + h) * DKh + dl) * Sq + s1;
                g_vt_hi[p00] = __float2bfloat16(v0); g_vt_hi[p00 + Sq] = __float2bfloat16(v1);
                g_vt_hi[p10] = __float2bfloat16(v2); g_vt_hi[p10 + Sq] = __float2bfloat16(v3);
            } else {
                int h = n >> 6, dl = n & 63;
                int b0_ = m0 >> 11, s0 = m0 & (Sq - 1);
                int b1_ = m1 >> 11, s1 = m1 & (Sq - 1);
                size_t o0 = ((size_t)(b0_ * Hh + h) * Sq + s0) * DKh + dl;
                size_t o1 = ((size_t)(b1_ * Hh + h) * Sq + s1) * DKh + dl;
                __nv_bfloat16* oh = (mode == 0) ? g_qh_hi : g_kh_hi;
                __nv_bfloat16* ol = (mode == 0) ? g_qh_lo : g_kh_lo;
                *(uint32_t*)(oh + o0) = pk(v0, v1);
                *(uint32_t*)(ol + o0) = pk(resid_f(v0), resid_f(v1));
                *(uint32_t*)(oh + o1) = pk(v2, v3);
                *(uint32_t*)(ol + o1) = pk(resid_f(v2), resid_f(v3));
            }
        }
    }
}

// ======================= flash attention (round-14 proven config) =======================
// grid (16, 32), 256 thr (8 warps). Tq=128 (warp: 16 rows), Tk=64, dk=64. OCC=1.
// Double-buffered k-tiles with rv/nv register prefetch; pipelined fragment loads.
// S: 3-pass (QhKh + QhKl + QlKh). PV: 2-pass (PhVh + PlVh).
#define AP 144
#define ATS 9216          // one k-tile: 64*144
#define ABUF (3*ATS)      // {Kh, Kl, Vh} = 27648
#define QTS  18432        // one Q half: 128*144
#define A_BASE 512
#define AT_SMEM (A_BASE + ABUF + 2*QTS)   // 65024
#define NKT (Sq/64)       // 32

__global__ __launch_bounds__(256, 1) void attn_tc() {
    extern __shared__ char smA[];
    const uint32_t smu = smem_u32(smA);
    const int t = threadIdx.x, lane = t & 31, wid = t >> 5;
    const int lr = lane >> 2, lc = lane & 3;
    const int bh = blockIdx.y, b = bh >> 3;
    const int qbase = blockIdx.x * 128;

    // ---- stage Q (hi/lo) beyond buffer 0, load into registers ----
    {
        char* qdst = smA + A_BASE + ABUF;
#pragma unroll
        for (int i = 0; i < 8; i++) {
            int id = t + i * 256;
            int half = id >> 10, w = id & 1023, row = w >> 3, sg = w & 7;
            const __nv_bfloat16* src = half ? g_qh_lo : g_qh_hi;
            *(uint4*)(qdst + half * QTS + row * AP + sg * 16) =
                *(const uint4*)(src + ((size_t)bh * Sq + qbase + row) * DKh + sg * 8);
        }
    }
    __syncthreads();

    uint32_t qhf[4][4], qlf[4][4];
    {
        uint32_t qb = smu + A_BASE + ABUF + (wid * 16 + (lane & 15)) * AP + (lane >> 4) * 16;
#pragma unroll
        for (int ks = 0; ks < 4; ks++) {
            ldsm4(qhf[ks], qb + ks * 32);
            ldsm4(qlf[ks], qb + ks * 32 + QTS);
        }
    }
    __syncthreads();

    uint4 rv[6], nv[6];
    float rew = 0.f, newv = 0.f;

    auto aload = [&](int kt, uint4* R, float& E) {
#pragma unroll
        for (int i = 0; i < 6; i++) {
            int id = t + i * 256;
            int tile = id >> 9, w = id & 511, row = w >> 3, sg = w & 7;
            const __nv_bfloat16* src;
            size_t g;
            if (tile == 0)      { src = g_kh_hi; g = ((size_t)bh * Sq + kt * 64 + row) * DKh + sg * 8; }
            else if (tile == 1) { src = g_kh_lo; g = ((size_t)bh * Sq + kt * 64 + row) * DKh + sg * 8; }
            else                { src = g_vt_hi; g = ((size_t)bh * DKh + row) * Sq + kt * 64 + sg * 8; }
            R[i] = *(const uint4*)(src + g);
        }
        if (t < 64) E = g_ew[(size_t)b * Sq + kt * 64 + t];
    };
    auto astore = [&](int kt, const uint4* R, float E) {
        char* dst = smA + A_BASE + (kt & 1) * ABUF;
#pragma unroll
        for (int i = 0; i < 6; i++) {
            int id = t + i * 256;
            int tile = id >> 9, w = id & 511, row = w >> 3, sg = w & 7;
            *(uint4*)(dst + tile * ATS + row * AP + sg * 16) = R[i];
        }
        if (t < 64) *(float*)(smA + (kt & 1) * 256 + t * 4) = E;
    };

    float O[8][4];
#pragma unroll
    for (int j = 0; j < 8; j++)
#pragma unroll
        for (int q = 0; q < 4; q++) O[j][q] = 0.f;
    float m0 = -1e30f, m1 = -1e30f, l0 = 0.f, l1 = 0.f;

    aload(0, rv, rew);

    for (int kt = 0; kt < NKT; kt++) {
        astore(kt, rv, rew);
        __syncthreads();
        if (kt + 1 < NKT) aload(kt + 1, nv, newv);

        uint32_t bK = smu + A_BASE + (kt & 1) * ABUF;

        // ---- S = Q K^T : pipelined fragment loads, K fragments reused by Qh/Ql ----
        float S[8][4];
#pragma unroll
        for (int j = 0; j < 8; j++)
#pragma unroll
            for (int q = 0; q < 4; q++) S[j][q] = 0.f;

        uint32_t kbh = bK + (lane & 15) * AP + (lane >> 4) * 16;
        uint32_t kbl = kbh + ATS;
        uint32_t kh4[2][4], kl4[2][4];
        ldsm4(kh4[0], kbh);
        ldsm4(kl4[0], kbl);
#pragma unroll
        for (int idx = 0; idx < 16; idx++) {
            int cur = idx & 1;
            if (idx < 15) {
                uint32_t off = (uint32_t)((idx + 1) & 3) * (16 * AP) + (uint32_t)((idx + 1) >> 2) * 32;
                ldsm4(kh4[cur ^ 1], kbh + off);
                ldsm4(kl4[cur ^ 1], kbl + off);
            }
            int ks = idx >> 2, j2 = idx & 3;
            {
                uint32_t be[2] = {kh4[cur][0], kh4[cur][2]}, bo[2] = {kh4[cur][1], kh4[cur][3]};
                mma16816(S[2 * j2],     qhf[ks], be);
                mma16816(S[2 * j2 + 1], qhf[ks], bo);
                mma16816(S[2 * j2],     qlf[ks], be);
                mma16816(S[2 * j2 + 1], qlf[ks], bo);
            }
            {
                uint32_t be[2] = {kl4[cur][0], kl4[cur][2]}, bo[2] = {kl4[cur][1], kl4[cur][3]};
                mma16816(S[2 * j2],     qhf[ks], be);
                mma16816(S[2 * j2 + 1], qhf[ks], bo);
            }
        }

        // ---- softmax (rows lr and lr+8, cols spread over 4 lanes) ----
        const float* ew = (const float*)(smA + (kt & 1) * 256);
        float mt0 = -1e30f, mt1 = -1e30f;
#pragma unroll
        for (int j = 0; j < 8; j++) {
            float2 e = *(const float2*)(ew + 8 * j + 2 * lc);
            S[j][0] *= e.x; S[j][1] *= e.y;
            S[j][2] *= e.x; S[j][3] *= e.y;
            mt0 = fmaxf(mt0, fmaxf(S[j][0], S[j][1]));
            mt1 = fmaxf(mt1, fmaxf(S[j][2], S[j][3]));
        }
        mt0 = fmaxf(mt0, __shfl_xor_sync(0xffffffffu, mt0, 1));
        mt0 = fmaxf(mt0, __shfl_xor_sync(0xffffffffu, mt0, 2));
        mt1 = fmaxf(mt1, __shfl_xor_sync(0xffffffffu, mt1, 1));
        mt1 = fmaxf(mt1, __shfl_xor_sync(0xffffffffu, mt1, 2));
        float mn0 = fmaxf(m0, mt0), mn1 = fmaxf(m1, mt1);
        float al0 = __expf(m0 - mn0), al1 = __expf(m1 - mn1);
        m0 = mn0; m1 = mn1;
        float ps0 = 0.f, ps1 = 0.f;
#pragma unroll
        for (int j = 0; j < 8; j++) {
            S[j][0] = __expf(S[j][0] - mn0); ps0 += S[j][0];
            S[j][1] = __expf(S[j][1] - mn0); ps0 += S[j][1];
            S[j][2] = __expf(S[j][2] - mn1); ps1 += S[j][2];
            S[j][3] = __expf(S[j][3] - mn1); ps1 += S[j][3];
        }
        ps0 += __shfl_xor_sync(0xffffffffu, ps0, 1);
        ps0 += __shfl_xor_sync(0xffffffffu, ps0, 2);
        ps1 += __shfl_xor_sync(0xffffffffu, ps1, 1);
        ps1 += __shfl_xor_sync(0xffffffffu, ps1, 2);
        l0 = l0 * al0 + ps0;
        l1 = l1 * al1 + ps1;
#pragma unroll
        for (int j = 0; j < 8; j++) {
            O[j][0] *= al0; O[j][1] *= al0;
            O[j][2] *= al1; O[j][3] *= al1;
        }

        // ---- P packs (hi/lo), reused directly as mma A operands ----
        uint32_t Ph[8][2], Pl[8][2];
#pragma unroll
        for (int j = 0; j < 8; j++) {
            Ph[j][0] = pk(S[j][0], S[j][1]);
            Ph[j][1] = pk(S[j][2], S[j][3]);
            Pl[j][0] = pk(resid_f(S[j][0]), resid_f(S[j][1]));
            Pl[j][1] = pk(resid_f(S[j][2]), resid_f(S[j][3]));
        }

        // ---- O += P V : 2-pass, pipelined V fragment loads ----
        uint32_t vbh = bK + 2 * ATS + (lane & 15) * AP + (lane >> 4) * 16;
        uint32_t vh4[2][4];
        ldsm4(vh4[0], vbh);
#pragma unroll
        for (int idx = 0; idx < 16; idx++) {
            int cur = idx & 1;
            if (idx < 15) {
                uint32_t off = (uint32_t)((idx + 1) & 3) * (16 * AP) + (uint32_t)((idx + 1) >> 2) * 32;
                ldsm4(vh4[cur ^ 1], vbh + off);
            }
            int ks = idx >> 2, j2 = idx & 3;
            uint32_t a4h[4] = {Ph[2 * ks][0], Ph[2 * ks][1], Ph[2 * ks + 1][0], Ph[2 * ks + 1][1]};
            uint32_t a4l[4] = {Pl[2 * ks][0], Pl[2 * ks][1], Pl[2 * ks + 1][0], Pl[2 * ks + 1][1]};
            uint32_t ve[2] = {vh4[cur][0], vh4[cur][2]}, vo[2] = {vh4[cur][1], vh4[cur][3]};
            mma16816(O[2 * j2],     a4h, ve);
            mma16816(O[2 * j2 + 1], a4h, vo);
            mma16816(O[2 * j2],     a4l, ve);
            mma16816(O[2 * j2 + 1], a4l, vo);
        }

#pragma unroll
        for (int i = 0; i < 6; i++) rv[i] = nv[i];
        rew = newv;
    }

    // ---- finalize + write fp32 into g_ao (B,S,512) ----
    float inv0 = 1.0f / l0, inv1 = 1.0f / l1;
    int row0 = qbase + wid * 16 + lr, row1 = row0 + 8;
    size_t base0 = ((size_t)(b * Sq + row0)) * Dm + (bh & 7) * DKh + 2 * lc;
    size_t base1 = ((size_t)(b * Sq + row1)) * Dm + (bh & 7) * DKh + 2 * lc;
#pragma unroll
    for (int j = 0; j < 8; j++) {
        *(float2*)(g_ao + base0 + 8 * j) = make_float2(O[j][0] * inv0, O[j][1] * inv0);
        *(float2*)(g_ao + base1 + 8 * j) = make_float2(O[j][2] * inv1, O[j][3] * inv1);
    }
}

// ======================= LayerNorm =======================
__global__ __launch_bounds__(128) void ln_kernel(const float* __restrict__ gamma,
                                                 const float* __restrict__ beta,
                                                 float* __restrict__ out) {
    __shared__ float red[4];
    const int row = blockIdx.x, t = threadIdx.x;
    float4 x = *(const float4*)(g_fc + (size_t)row * Dm + t * 4);
    float s = x.x + x.y + x.z + x.w;
#pragma unroll
    for (int off = 16; off > 0; off >>= 1) s += __shfl_xor_sync(0xffffffffu, s, off);
    if ((t & 31) == 0) red[t >> 5] = s;
    __syncthreads();
    float mu = (red[0] + red[1] + red[2] + red[3]) * (1.0f / Dm);
    float d0 = x.x - mu, d1 = x.y - mu, d2 = x.z - mu, d3 = x.w - mu;
    float sq = d0 * d0 + d1 * d1 + d2 * d2 + d3 * d3;
#pragma unroll
    for (int off = 16; off > 0; off >>= 1) sq += __shfl_xor_sync(0xffffffffu, sq, off);
    __syncthreads();
    if ((t & 31) == 0) red[t >> 5] = sq;
    __syncthreads();
    float var = (red[0] + red[1] + red[2] + red[3]) * (1.0f / Dm);
    float inv = rsqrtf(var + 1e-5f);
    int c = t * 4;
    float4 g = *(const float4*)(gamma + c);
    float4 be = *(const float4*)(beta + c);
    *(float4*)(out + (size_t)row * Dm + c) =
        make_float4(d0 * inv * g.x + be.x, d1 * inv * g.y + be.y,
                    d2 * inv * g.z + be.z, d3 * inv * g.w + be.w);
}

// ======================= launch =======================
extern "C" void kernel_launch(void* const* d_in, const int* in_sizes, int n_in,
                              void* d_out, int out_size) {
    const float* Q   = (const float*)d_in[0];
    const float* K   = (const float*)d_in[1];
    const float* V   = (const float*)d_in[2];
    const float* ent = (const float*)d_in[3];
    const float* Wq  = (const float*)d_in[4];
    const float* bq  = (const float*)d_in[5];
    const float* Wk  = (const float*)d_in[6];
    const float* bk  = (const float*)d_in[7];
    const float* Wv  = (const float*)d_in[8];
    const float* bv  = (const float*)d_in[9];
    const float* Wfc = (const float*)d_in[10];
    const float* bfc = (const float*)d_in[11];
    const float* We  = (const float*)d_in[12];
    const float* gam = (const float*)d_in[13];
    const float* bet = (const float*)d_in[14];
    float* out = (float*)d_out;

    cudaFuncSetAttribute(attn_tc, cudaFuncAttributeMaxDynamicSharedMemorySize, AT_SMEM);
    cudaFuncSetAttribute(gemm_tc, cudaFuncAttributeMaxDynamicSharedMemorySize, GSMEM);

    ew_kernel<<<(Bz * Sq) / 256, 256>>>(We, ent);
    wsplit_kernel<<<dim3(256, 4), 256>>>(Wq, Wk, Wv, Wfc);

    // fused QKV projections: one launch, blockIdx.z = mode
    gemm_tc<<<dim3(Dm / 128, Mrows / 128, 3), 256, GSMEM>>>(Q, K, V, bq, bk, bv, nullptr, -1);

    attn_tc<<<dim3(Sq / 128, Bz * Hh), 256, AT_SMEM>>>();

    gemm_tc<<<dim3(Dm / 128, Mrows / 128, 1), 256, GSMEM>>>(nullptr, nullptr, nullptr,
                                                            bfc, nullptr, nullptr, Q, 3);
    ln_kernel<<<Mrows, 128>>>(gam, bet, out);
}